// round 1
// baseline (speedup 1.0000x reference)
#include <cuda_runtime.h>
#include <cstddef>

#define NN 100000
#define NE 1600000

// Scratch (static __device__ allocation is allowed; cudaMalloc is not)
__device__ float g_y[(size_t)NN * 128];    // h @ Wl^T  (to be aggregated)
__device__ float g_z[(size_t)NN * 128];    // h @ Wr^T  (root term)
__device__ float g_agg[(size_t)NN * 128];  // segment sum
__device__ float g_h1[(size_t)NN * 128];   // layer-0 output
__device__ float g_h2[(size_t)NN * 128];   // layer-1 output
__device__ float g_cnt[NN];                // in-degree (float)

// ---------------------------------------------------------------------------
__global__ void zero_f4(float4* __restrict__ p, int n4) {
    int i = blockIdx.x * blockDim.x + threadIdx.x;
    if (i < n4) p[i] = make_float4(0.f, 0.f, 0.f, 0.f);
}

__global__ void count_deg(const int* __restrict__ dst, float* __restrict__ cnt) {
    int e = blockIdx.x * blockDim.x + threadIdx.x;
    if (e < NE) atomicAdd(cnt + dst[e], 1.0f);   // compiles to RED (no return use)
}

// One float4 per thread; C4 = cols/4 (32 or 16). Consecutive threads cover one
// edge's full row -> coalesced gather and coalesced vector-RED scatter.
template <int C4>
__global__ void scatter_add(const float4* __restrict__ y,
                            const int* __restrict__ src,
                            const int* __restrict__ dst,
                            float* __restrict__ agg) {
    unsigned int tid = blockIdx.x * blockDim.x + threadIdx.x;
    unsigned int e = tid / C4;
    unsigned int c = tid % C4;
    if (e >= NE) return;
    int s = src[e];
    int d = dst[e];
    float4 v = y[(size_t)s * C4 + c];
    float* p = agg + ((size_t)d * C4 + c) * 4;
    asm volatile("red.global.add.v4.f32 [%0], {%1, %2, %3, %4};"
                 :: "l"(p), "f"(v.x), "f"(v.y), "f"(v.z), "f"(v.w)
                 : "memory");
}

// ---------------------------------------------------------------------------
// C[M,N] = A[M,128] * B[N,128]^T   (both K-contiguous; NT gemm)
// BM=BN=64, BK=16, 256 threads, 4x4 register tile per thread.
__global__ __launch_bounds__(256) void sgemm_nt(
    const float* __restrict__ A, const float* __restrict__ B,
    float* __restrict__ C, int M, int N) {
    __shared__ float As[16][64];
    __shared__ float Bs[16][64];

    const int bm0 = blockIdx.y * 64;
    const int bn0 = blockIdx.x * 64;
    const int tid = threadIdx.x;
    const int lrow = tid >> 2;          // 0..63
    const int lc4  = (tid & 3) << 2;    // 0,4,8,12
    const int tx = tid & 15;            // output col group
    const int ty = tid >> 4;            // output row group

    float acc[4][4] = {};

    const bool aok = (bm0 + lrow) < M;  // grid.x exact in N, only M needs guard
    const float* Ap = A + (size_t)(bm0 + lrow) * 128 + lc4;
    const float* Bp = B + (size_t)(bn0 + lrow) * 128 + lc4;

    #pragma unroll
    for (int k0 = 0; k0 < 128; k0 += 16) {
        float4 a4 = aok ? *(const float4*)(Ap + k0) : make_float4(0.f, 0.f, 0.f, 0.f);
        float4 b4 = *(const float4*)(Bp + k0);
        As[lc4 + 0][lrow] = a4.x;
        As[lc4 + 1][lrow] = a4.y;
        As[lc4 + 2][lrow] = a4.z;
        As[lc4 + 3][lrow] = a4.w;
        Bs[lc4 + 0][lrow] = b4.x;
        Bs[lc4 + 1][lrow] = b4.y;
        Bs[lc4 + 2][lrow] = b4.z;
        Bs[lc4 + 3][lrow] = b4.w;
        __syncthreads();

        #pragma unroll
        for (int k = 0; k < 16; k++) {
            float4 am = *(const float4*)&As[k][ty * 4];
            float4 bn = *(const float4*)&Bs[k][tx * 4];
            acc[0][0] += am.x * bn.x; acc[0][1] += am.x * bn.y;
            acc[0][2] += am.x * bn.z; acc[0][3] += am.x * bn.w;
            acc[1][0] += am.y * bn.x; acc[1][1] += am.y * bn.y;
            acc[1][2] += am.y * bn.z; acc[1][3] += am.y * bn.w;
            acc[2][0] += am.z * bn.x; acc[2][1] += am.z * bn.y;
            acc[2][2] += am.z * bn.z; acc[2][3] += am.z * bn.w;
            acc[3][0] += am.w * bn.x; acc[3][1] += am.w * bn.y;
            acc[3][2] += am.w * bn.z; acc[3][3] += am.w * bn.w;
        }
        __syncthreads();
    }

    #pragma unroll
    for (int i = 0; i < 4; i++) {
        int row = bm0 + ty * 4 + i;
        if (row < M) {
            float4 o = make_float4(acc[i][0], acc[i][1], acc[i][2], acc[i][3]);
            *(float4*)(C + (size_t)row * N + bn0 + tx * 4) = o;
        }
    }
}

// ---------------------------------------------------------------------------
// out = [relu]( agg / max(deg,1) + z + b )
template <int C4, bool RELU>
__global__ void combine_k(const float4* __restrict__ agg,
                          const float4* __restrict__ z,
                          const float* __restrict__ b,
                          const float* __restrict__ cnt,
                          float4* __restrict__ out) {
    int i = blockIdx.x * blockDim.x + threadIdx.x;
    if (i >= NN * C4) return;
    int node = i / C4;
    int c = i % C4;
    float inv = 1.0f / fmaxf(cnt[node], 1.0f);
    float4 a = agg[i];
    float4 zz = z[i];
    float4 bb = ((const float4*)b)[c];
    float4 o;
    o.x = a.x * inv + zz.x + bb.x;
    o.y = a.y * inv + zz.y + bb.y;
    o.z = a.z * inv + zz.z + bb.z;
    o.w = a.w * inv + zz.w + bb.w;
    if (RELU) {
        o.x = fmaxf(o.x, 0.f);
        o.y = fmaxf(o.y, 0.f);
        o.z = fmaxf(o.z, 0.f);
        o.w = fmaxf(o.w, 0.f);
    }
    out[i] = o;
}

// ---------------------------------------------------------------------------
extern "C" void kernel_launch(void* const* d_in, const int* in_sizes, int n_in,
                              void* d_out, int out_size) {
    const float* x   = (const float*)d_in[0];
    const int*   ei  = (const int*)d_in[1];
    const float* Wl0 = (const float*)d_in[2];
    const float* Wr0 = (const float*)d_in[3];
    const float* b0  = (const float*)d_in[4];
    const float* Wl1 = (const float*)d_in[5];
    const float* Wr1 = (const float*)d_in[6];
    const float* b1  = (const float*)d_in[7];
    const float* Wl2 = (const float*)d_in[8];
    const float* Wr2 = (const float*)d_in[9];
    const float* b2  = (const float*)d_in[10];
    float* out = (float*)d_out;

    const int* src = ei;        // edge_index[0]
    const int* dst = ei + NE;   // edge_index[1]

    float *y, *z, *agg, *h1, *h2, *cnt;
    cudaGetSymbolAddress((void**)&y,   g_y);
    cudaGetSymbolAddress((void**)&z,   g_z);
    cudaGetSymbolAddress((void**)&agg, g_agg);
    cudaGetSymbolAddress((void**)&h1,  g_h1);
    cudaGetSymbolAddress((void**)&h2,  g_h2);
    cudaGetSymbolAddress((void**)&cnt, g_cnt);

    const int T = 256;
    dim3 g128(2, (NN + 63) / 64);
    dim3 g64(1, (NN + 63) / 64);

    // in-degree
    zero_f4<<<(NN / 4 + T - 1) / T, T>>>((float4*)cnt, NN / 4);
    count_deg<<<(NE + T - 1) / T, T>>>(dst, cnt);

    // ---- layer 0 (relu) ----
    sgemm_nt<<<g128, T>>>(x, Wl0, y, NN, 128);
    sgemm_nt<<<g128, T>>>(x, Wr0, z, NN, 128);
    zero_f4<<<(NN * 32 + T - 1) / T, T>>>((float4*)agg, NN * 32);
    scatter_add<32><<<((unsigned)NE * 32 + T - 1) / T, T>>>((const float4*)y, src, dst, agg);
    combine_k<32, true><<<(NN * 32 + T - 1) / T, T>>>(
        (const float4*)agg, (const float4*)z, b0, cnt, (float4*)h1);

    // ---- layer 1 (relu) ----
    sgemm_nt<<<g128, T>>>(h1, Wl1, y, NN, 128);
    sgemm_nt<<<g128, T>>>(h1, Wr1, z, NN, 128);
    zero_f4<<<(NN * 32 + T - 1) / T, T>>>((float4*)agg, NN * 32);
    scatter_add<32><<<((unsigned)NE * 32 + T - 1) / T, T>>>((const float4*)y, src, dst, agg);
    combine_k<32, true><<<(NN * 32 + T - 1) / T, T>>>(
        (const float4*)agg, (const float4*)z, b1, cnt, (float4*)h2);

    // ---- layer 2 (no act, d_out = 64) ----
    sgemm_nt<<<g64, T>>>(h2, Wl2, y, NN, 64);
    sgemm_nt<<<g64, T>>>(h2, Wr2, z, NN, 64);
    zero_f4<<<(NN * 16 + T - 1) / T, T>>>((float4*)agg, NN * 16);
    scatter_add<16><<<((unsigned)NE * 16 + T - 1) / T, T>>>((const float4*)y, src, dst, agg);
    combine_k<16, false><<<(NN * 16 + T - 1) / T, T>>>(
        (const float4*)agg, (const float4*)z, b2, cnt, (float4*)out);
}

// round 2
// speedup vs baseline: 1.5036x; 1.5036x over previous
#include <cuda_runtime.h>
#include <cstddef>

#define NN 100000
#define NE 1600000
#define SCAN_B 1024
#define NBLK ((NN + SCAN_B - 1) / SCAN_B)   // 98

// ---------------- scratch (static device allocations) ----------------------
__device__ float g_yz[(size_t)NN * 256];   // [y | z] per node (fused GEMM out)
__device__ float g_h[(size_t)NN * 128];    // hidden activations (reused)
__device__ float g_wcat[256 * 128];        // [Wl ; Wr] concat per layer
__device__ int   g_cnt[NN];                // in-degree
__device__ int   g_offs[NN + 1];           // CSR row offsets
__device__ int   g_cursor[NN];             // placement cursors
__device__ int   g_csrc[NE];               // src ids sorted by dst
__device__ int   g_bsum[NBLK];             // scan block sums

// ---------------------------------------------------------------------------
__global__ void count_deg(const int* __restrict__ dst, int* __restrict__ cnt) {
    int e = blockIdx.x * blockDim.x + threadIdx.x;
    if (e < NE) atomicAdd(cnt + dst[e], 1);
}
__global__ void zero_cnt(int* __restrict__ cnt) {
    int i = blockIdx.x * blockDim.x + threadIdx.x;
    if (i < NN) cnt[i] = 0;
}

// exclusive scan, phase A: per-block scan + block totals
__global__ void scan_a(const int* __restrict__ cnt, int* __restrict__ offs,
                       int* __restrict__ bsum) {
    __shared__ int sh[SCAN_B];
    int gid = blockIdx.x * SCAN_B + threadIdx.x;
    int v = (gid < NN) ? cnt[gid] : 0;
    sh[threadIdx.x] = v;
    __syncthreads();
    for (int d = 1; d < SCAN_B; d <<= 1) {
        int t = (threadIdx.x >= d) ? sh[threadIdx.x - d] : 0;
        __syncthreads();
        sh[threadIdx.x] += t;
        __syncthreads();
    }
    if (gid < NN) offs[gid] = sh[threadIdx.x] - v;   // exclusive
    if (threadIdx.x == SCAN_B - 1) bsum[blockIdx.x] = sh[threadIdx.x];
}
// phase B: scan block totals (NBLK <= 128)
__global__ void scan_b(int* __restrict__ bsum) {
    __shared__ int sh[128];
    int v = (threadIdx.x < NBLK) ? bsum[threadIdx.x] : 0;
    sh[threadIdx.x] = v;
    __syncthreads();
    for (int d = 1; d < 128; d <<= 1) {
        int t = (threadIdx.x >= d) ? sh[threadIdx.x - d] : 0;
        __syncthreads();
        sh[threadIdx.x] += t;
        __syncthreads();
    }
    if (threadIdx.x < NBLK) bsum[threadIdx.x] = sh[threadIdx.x] - v;
}
// phase C: add block offsets, init cursors
__global__ void scan_c(int* __restrict__ offs, const int* __restrict__ bsum,
                       int* __restrict__ cursor) {
    int gid = blockIdx.x * blockDim.x + threadIdx.x;
    if (gid < NN) {
        int o = offs[gid] + bsum[gid >> 10];
        offs[gid] = o;
        cursor[gid] = o;
    }
    if (gid == 0) offs[NN] = NE;
}
__global__ void place_edges(const int* __restrict__ src, const int* __restrict__ dst,
                            int* __restrict__ cursor, int* __restrict__ csrc) {
    int e = blockIdx.x * blockDim.x + threadIdx.x;
    if (e < NE) {
        int p = atomicAdd(cursor + dst[e], 1);
        csrc[p] = src[e];
    }
}

// ---------------------------------------------------------------------------
// C[M,N] = A[M,128] * B[N,128]^T ; BM=BN=128, BK=8, 256 thr, 8x8 microtile,
// double-buffered smem.
__global__ __launch_bounds__(256, 2) void sgemm128(
    const float* __restrict__ A, const float* __restrict__ B,
    float* __restrict__ C, int M, int N) {
    __shared__ float As[2][8][128];
    __shared__ float Bs[2][8][128];

    const int tid = threadIdx.x;
    const int bm0 = blockIdx.y * 128;
    const int bn0 = blockIdx.x * 128;
    const int lrow = tid >> 1;           // 0..127
    const int lk = (tid & 1) * 4;        // 0 or 4
    const int tx = tid & 15;
    const int ty = tid >> 4;

    const bool aok = (bm0 + lrow) < M;
    const float* Ap = A + (size_t)(bm0 + lrow) * 128 + lk;
    const float* Bp = B + (size_t)(bn0 + lrow) * 128 + lk;

    float4 a4 = aok ? *(const float4*)Ap : make_float4(0.f, 0.f, 0.f, 0.f);
    float4 b4 = *(const float4*)Bp;
    As[0][lk + 0][lrow] = a4.x; As[0][lk + 1][lrow] = a4.y;
    As[0][lk + 2][lrow] = a4.z; As[0][lk + 3][lrow] = a4.w;
    Bs[0][lk + 0][lrow] = b4.x; Bs[0][lk + 1][lrow] = b4.y;
    Bs[0][lk + 2][lrow] = b4.z; Bs[0][lk + 3][lrow] = b4.w;
    __syncthreads();

    float acc[8][8] = {};

    #pragma unroll
    for (int t = 0; t < 16; t++) {
        const int cur = t & 1;
        if (t < 15) {
            const float* Ap2 = Ap + (t + 1) * 8;
            const float* Bp2 = Bp + (t + 1) * 8;
            a4 = aok ? *(const float4*)Ap2 : make_float4(0.f, 0.f, 0.f, 0.f);
            b4 = *(const float4*)Bp2;
        }
        #pragma unroll
        for (int k = 0; k < 8; k++) {
            float4 am0 = *(const float4*)&As[cur][k][ty * 4];
            float4 am1 = *(const float4*)&As[cur][k][64 + ty * 4];
            float4 bn0v = *(const float4*)&Bs[cur][k][tx * 4];
            float4 bn1v = *(const float4*)&Bs[cur][k][64 + tx * 4];
            float ar[8] = {am0.x, am0.y, am0.z, am0.w, am1.x, am1.y, am1.z, am1.w};
            float br[8] = {bn0v.x, bn0v.y, bn0v.z, bn0v.w, bn1v.x, bn1v.y, bn1v.z, bn1v.w};
            #pragma unroll
            for (int i = 0; i < 8; i++)
                #pragma unroll
                for (int j = 0; j < 8; j++)
                    acc[i][j] += ar[i] * br[j];
        }
        if (t < 15) {
            const int nxt = cur ^ 1;
            As[nxt][lk + 0][lrow] = a4.x; As[nxt][lk + 1][lrow] = a4.y;
            As[nxt][lk + 2][lrow] = a4.z; As[nxt][lk + 3][lrow] = a4.w;
            Bs[nxt][lk + 0][lrow] = b4.x; Bs[nxt][lk + 1][lrow] = b4.y;
            Bs[nxt][lk + 2][lrow] = b4.z; Bs[nxt][lk + 3][lrow] = b4.w;
            __syncthreads();
        }
    }

    #pragma unroll
    for (int i = 0; i < 8; i++) {
        int row = bm0 + (i < 4 ? ty * 4 + i : 64 + ty * 4 + (i - 4));
        if (row < M) {
            float* Cp = C + (size_t)row * N + bn0;
            *(float4*)(Cp + tx * 4) = make_float4(acc[i][0], acc[i][1], acc[i][2], acc[i][3]);
            *(float4*)(Cp + 64 + tx * 4) = make_float4(acc[i][4], acc[i][5], acc[i][6], acc[i][7]);
        }
    }
}

// ---------------------------------------------------------------------------
// Fused: out = [relu]( mean_{j in CSR[i]} y_j + z_i + b ), y/z packed in yz.
// C4 lanes per node, each lane owns one float4 column group.
template <int C4, bool RELU>
__global__ void agg_combine(const float4* __restrict__ yz,
                            const int* __restrict__ csrc,
                            const int* __restrict__ offs,
                            const float* __restrict__ b,
                            float4* __restrict__ out) {
    const int S4 = 2 * C4;  // yz row stride in float4
    int gid = blockIdx.x * blockDim.x + threadIdx.x;
    int node = gid / C4;
    int lane = gid % C4;
    if (node >= NN) return;

    int s = offs[node], e = offs[node + 1];
    float4 acc = make_float4(0.f, 0.f, 0.f, 0.f);
    int i = s;
    for (; i + 1 < e; i += 2) {
        int s0 = csrc[i], s1 = csrc[i + 1];
        float4 v0 = yz[(size_t)s0 * S4 + lane];
        float4 v1 = yz[(size_t)s1 * S4 + lane];
        acc.x += v0.x + v1.x; acc.y += v0.y + v1.y;
        acc.z += v0.z + v1.z; acc.w += v0.w + v1.w;
    }
    if (i < e) {
        float4 v = yz[(size_t)csrc[i] * S4 + lane];
        acc.x += v.x; acc.y += v.y; acc.z += v.z; acc.w += v.w;
    }
    float inv = 1.0f / (float)max(e - s, 1);
    float4 z = yz[(size_t)node * S4 + C4 + lane];
    float4 bb = ((const float4*)b)[lane];
    float4 o;
    o.x = acc.x * inv + z.x + bb.x;
    o.y = acc.y * inv + z.y + bb.y;
    o.z = acc.z * inv + z.z + bb.z;
    o.w = acc.w * inv + z.w + bb.w;
    if (RELU) {
        o.x = fmaxf(o.x, 0.f); o.y = fmaxf(o.y, 0.f);
        o.z = fmaxf(o.z, 0.f); o.w = fmaxf(o.w, 0.f);
    }
    out[(size_t)node * C4 + lane] = o;
}

// ---------------------------------------------------------------------------
extern "C" void kernel_launch(void* const* d_in, const int* in_sizes, int n_in,
                              void* d_out, int out_size) {
    const float* x   = (const float*)d_in[0];
    const int*   ei  = (const int*)d_in[1];
    const float* Wl0 = (const float*)d_in[2];
    const float* Wr0 = (const float*)d_in[3];
    const float* b0  = (const float*)d_in[4];
    const float* Wl1 = (const float*)d_in[5];
    const float* Wr1 = (const float*)d_in[6];
    const float* b1  = (const float*)d_in[7];
    const float* Wl2 = (const float*)d_in[8];
    const float* Wr2 = (const float*)d_in[9];
    const float* b2  = (const float*)d_in[10];
    float* out = (float*)d_out;

    const int* src = ei;
    const int* dst = ei + NE;

    float *yz, *h, *wcat;
    int *cnt, *offs, *cursor, *csrc, *bsum;
    cudaGetSymbolAddress((void**)&yz,     g_yz);
    cudaGetSymbolAddress((void**)&h,      g_h);
    cudaGetSymbolAddress((void**)&wcat,   g_wcat);
    cudaGetSymbolAddress((void**)&cnt,    g_cnt);
    cudaGetSymbolAddress((void**)&offs,   g_offs);
    cudaGetSymbolAddress((void**)&cursor, g_cursor);
    cudaGetSymbolAddress((void**)&csrc,   g_csrc);
    cudaGetSymbolAddress((void**)&bsum,   g_bsum);

    const int T = 256;
    const size_t WSZ = 128 * 128 * sizeof(float);

    // ---- build CSR (edges -> sorted-by-dst src list) ----
    zero_cnt<<<(NN + T - 1) / T, T>>>(cnt);
    count_deg<<<(NE + T - 1) / T, T>>>(dst, cnt);
    scan_a<<<NBLK, SCAN_B>>>(cnt, offs, bsum);
    scan_b<<<1, 128>>>(bsum);
    scan_c<<<(NN + T - 1) / T, T>>>(offs, bsum, cursor);
    place_edges<<<(NE + T - 1) / T, T>>>(src, dst, cursor, csrc);

    dim3 gM(2, (NN + 127) / 128);   // N = 256
    dim3 gM1(1, (NN + 127) / 128);  // N = 128

    // ---- layer 0 ----
    cudaMemcpyAsync(wcat, Wl0, WSZ, cudaMemcpyDeviceToDevice);
    cudaMemcpyAsync(wcat + 128 * 128, Wr0, WSZ, cudaMemcpyDeviceToDevice);
    sgemm128<<<gM, T>>>(x, wcat, yz, NN, 256);
    agg_combine<32, true><<<(NN * 32 + T - 1) / T, T>>>(
        (const float4*)yz, csrc, offs, b0, (float4*)h);

    // ---- layer 1 ----
    cudaMemcpyAsync(wcat, Wl1, WSZ, cudaMemcpyDeviceToDevice);
    cudaMemcpyAsync(wcat + 128 * 128, Wr1, WSZ, cudaMemcpyDeviceToDevice);
    sgemm128<<<gM, T>>>(h, wcat, yz, NN, 256);
    agg_combine<32, true><<<(NN * 32 + T - 1) / T, T>>>(
        (const float4*)yz, csrc, offs, b1, (float4*)h);

    // ---- layer 2 (d_out = 64, no relu) ----
    cudaMemcpyAsync(wcat, Wl2, WSZ / 2, cudaMemcpyDeviceToDevice);
    cudaMemcpyAsync(wcat + 64 * 128, Wr2, WSZ / 2, cudaMemcpyDeviceToDevice);
    sgemm128<<<gM1, T>>>(h, wcat, yz, NN, 128);
    agg_combine<16, false><<<(NN * 16 + T - 1) / T, T>>>(
        (const float4*)yz, csrc, offs, b2, (float4*)out);
}

// round 3
// speedup vs baseline: 1.8768x; 1.2482x over previous
#include <cuda_runtime.h>
#include <mma.h>
#include <cstddef>

using namespace nvcuda;

#define NN 100000
#define NN_PAD 100096            // 782 * 128 (padded for unguarded GEMM stores)
#define NE 1600000
#define SCAN_B 1024
#define NBLK ((NN + SCAN_B - 1) / SCAN_B)   // 98

// ---------------- scratch (static device allocations) ----------------------
__device__ float g_yz[(size_t)NN_PAD * 256]; // [y | z] per node (fused GEMM out)
__device__ float g_h[(size_t)NN_PAD * 128];  // hidden activations (reused)
__device__ float g_wcat[256 * 128];          // [Wl ; Wr] concat per layer
__device__ int   g_cnt[NN];
__device__ int   g_offs[NN + 1];
__device__ int   g_cursor[NN];
__device__ int   g_csrc[NE];
__device__ int   g_bsum[NBLK];

// ---------------------------------------------------------------------------
__global__ void count_deg(const int* __restrict__ dst, int* __restrict__ cnt) {
    int e = blockIdx.x * blockDim.x + threadIdx.x;
    if (e < NE) atomicAdd(cnt + dst[e], 1);
}
__global__ void zero_cnt(int* __restrict__ cnt) {
    int i = blockIdx.x * blockDim.x + threadIdx.x;
    if (i < NN) cnt[i] = 0;
}

__global__ void scan_a(const int* __restrict__ cnt, int* __restrict__ offs,
                       int* __restrict__ bsum) {
    __shared__ int sh[SCAN_B];
    int gid = blockIdx.x * SCAN_B + threadIdx.x;
    int v = (gid < NN) ? cnt[gid] : 0;
    sh[threadIdx.x] = v;
    __syncthreads();
    for (int d = 1; d < SCAN_B; d <<= 1) {
        int t = (threadIdx.x >= d) ? sh[threadIdx.x - d] : 0;
        __syncthreads();
        sh[threadIdx.x] += t;
        __syncthreads();
    }
    if (gid < NN) offs[gid] = sh[threadIdx.x] - v;
    if (threadIdx.x == SCAN_B - 1) bsum[blockIdx.x] = sh[threadIdx.x];
}
__global__ void scan_b(int* __restrict__ bsum) {
    __shared__ int sh[128];
    int v = (threadIdx.x < NBLK) ? bsum[threadIdx.x] : 0;
    sh[threadIdx.x] = v;
    __syncthreads();
    for (int d = 1; d < 128; d <<= 1) {
        int t = (threadIdx.x >= d) ? sh[threadIdx.x - d] : 0;
        __syncthreads();
        sh[threadIdx.x] += t;
        __syncthreads();
    }
    if (threadIdx.x < NBLK) bsum[threadIdx.x] = sh[threadIdx.x] - v;
}
__global__ void scan_c(int* __restrict__ offs, const int* __restrict__ bsum,
                       int* __restrict__ cursor) {
    int gid = blockIdx.x * blockDim.x + threadIdx.x;
    if (gid < NN) {
        int o = offs[gid] + bsum[gid >> 10];
        offs[gid] = o;
        cursor[gid] = o;
    }
    if (gid == 0) offs[NN] = NE;
}
__global__ void place_edges(const int* __restrict__ src, const int* __restrict__ dst,
                            int* __restrict__ cursor, int* __restrict__ csrc) {
    int e = blockIdx.x * blockDim.x + threadIdx.x;
    if (e < NE) {
        int p = atomicAdd(cursor + dst[e], 1);
        csrc[p] = src[e];
    }
}

// ---------------------------------------------------------------------------
// TF32 tensor-core GEMM: C[M_pad, N] = A[M,128] * B[N,128]^T.
// Block tile 128x64, 8 warps (4x2), warp tile 32x32 (2x2 wmma m16n16k8).
// Stores are unguarded (C buffers padded to NN_PAD rows); A loads guarded at M.
#define BK 16
#define LDT (BK + 8)

__global__ __launch_bounds__(256) void tf32gemm(
    const float* __restrict__ A, const float* __restrict__ B,
    float* __restrict__ C, int M, int N) {
    __shared__ float As[128][LDT];
    __shared__ float Bs[64][LDT];

    const int tid = threadIdx.x;
    const int warp = tid >> 5;
    const int wm = warp & 3;     // 0..3 -> m offset 32*wm
    const int wn = warp >> 2;    // 0..1 -> n offset 32*wn
    const int bm0 = blockIdx.y * 128;
    const int bn0 = blockIdx.x * 64;

    wmma::fragment<wmma::accumulator, 16, 16, 8, float> acc[2][2];
    #pragma unroll
    for (int i = 0; i < 2; i++)
        #pragma unroll
        for (int j = 0; j < 2; j++)
            wmma::fill_fragment(acc[i][j], 0.0f);

    // A loader: 512 float4s, 2 per thread. B loader: 256 float4s, 1 per thread.
    const int af0 = tid * 2;
    const int arow0 = af0 >> 2, ac0 = (af0 & 3) * 4;
    const int arow1 = (af0 + 1) >> 2, ac1 = ((af0 + 1) & 3) * 4;
    const int brow = tid >> 2, bc = (tid & 3) * 4;
    const bool aok0 = (bm0 + arow0) < M;
    const bool aok1 = (bm0 + arow1) < M;

    for (int k0 = 0; k0 < 128; k0 += BK) {
        float4 a0 = aok0 ? *(const float4*)(A + (size_t)(bm0 + arow0) * 128 + k0 + ac0)
                         : make_float4(0.f, 0.f, 0.f, 0.f);
        float4 a1 = aok1 ? *(const float4*)(A + (size_t)(bm0 + arow1) * 128 + k0 + ac1)
                         : make_float4(0.f, 0.f, 0.f, 0.f);
        float4 b4 = *(const float4*)(B + (size_t)(bn0 + brow) * 128 + k0 + bc);

        As[arow0][ac0 + 0] = wmma::__float_to_tf32(a0.x);
        As[arow0][ac0 + 1] = wmma::__float_to_tf32(a0.y);
        As[arow0][ac0 + 2] = wmma::__float_to_tf32(a0.z);
        As[arow0][ac0 + 3] = wmma::__float_to_tf32(a0.w);
        As[arow1][ac1 + 0] = wmma::__float_to_tf32(a1.x);
        As[arow1][ac1 + 1] = wmma::__float_to_tf32(a1.y);
        As[arow1][ac1 + 2] = wmma::__float_to_tf32(a1.z);
        As[arow1][ac1 + 3] = wmma::__float_to_tf32(a1.w);
        Bs[brow][bc + 0] = wmma::__float_to_tf32(b4.x);
        Bs[brow][bc + 1] = wmma::__float_to_tf32(b4.y);
        Bs[brow][bc + 2] = wmma::__float_to_tf32(b4.z);
        Bs[brow][bc + 3] = wmma::__float_to_tf32(b4.w);
        __syncthreads();

        #pragma unroll
        for (int kk = 0; kk < BK; kk += 8) {
            wmma::fragment<wmma::matrix_a, 16, 16, 8, wmma::precision::tf32,
                           wmma::row_major> af[2];
            wmma::fragment<wmma::matrix_b, 16, 16, 8, wmma::precision::tf32,
                           wmma::col_major> bf[2];
            wmma::load_matrix_sync(af[0], &As[wm * 32 + 0][kk], LDT);
            wmma::load_matrix_sync(af[1], &As[wm * 32 + 16][kk], LDT);
            wmma::load_matrix_sync(bf[0], &Bs[wn * 32 + 0][kk], LDT);
            wmma::load_matrix_sync(bf[1], &Bs[wn * 32 + 16][kk], LDT);
            #pragma unroll
            for (int i = 0; i < 2; i++)
                #pragma unroll
                for (int j = 0; j < 2; j++)
                    wmma::mma_sync(acc[i][j], af[i], bf[j], acc[i][j]);
        }
        __syncthreads();
    }

    #pragma unroll
    for (int i = 0; i < 2; i++)
        #pragma unroll
        for (int j = 0; j < 2; j++) {
            int row0 = bm0 + wm * 32 + i * 16;
            int col0 = bn0 + wn * 32 + j * 16;
            wmma::store_matrix_sync(C + (size_t)row0 * N + col0, acc[i][j], N,
                                    wmma::mem_row_major);
        }
}

// ---------------------------------------------------------------------------
// Fused: out = [relu]( mean_{j in CSR[i]} y_j + z_i + b ), y/z packed in yz.
template <int C4, bool RELU>
__global__ void agg_combine(const float4* __restrict__ yz,
                            const int* __restrict__ csrc,
                            const int* __restrict__ offs,
                            const float* __restrict__ b,
                            float4* __restrict__ out) {
    const int S4 = 2 * C4;
    int gid = blockIdx.x * blockDim.x + threadIdx.x;
    int node = gid / C4;
    int lane = gid % C4;
    if (node >= NN) return;

    int s = offs[node], e = offs[node + 1];
    float4 acc = make_float4(0.f, 0.f, 0.f, 0.f);
    int i = s;
    for (; i + 1 < e; i += 2) {
        int s0 = csrc[i], s1 = csrc[i + 1];
        float4 v0 = yz[(size_t)s0 * S4 + lane];
        float4 v1 = yz[(size_t)s1 * S4 + lane];
        acc.x += v0.x + v1.x; acc.y += v0.y + v1.y;
        acc.z += v0.z + v1.z; acc.w += v0.w + v1.w;
    }
    if (i < e) {
        float4 v = yz[(size_t)csrc[i] * S4 + lane];
        acc.x += v.x; acc.y += v.y; acc.z += v.z; acc.w += v.w;
    }
    float inv = 1.0f / (float)max(e - s, 1);
    float4 z = yz[(size_t)node * S4 + C4 + lane];
    float4 bb = ((const float4*)b)[lane];
    float4 o;
    o.x = acc.x * inv + z.x + bb.x;
    o.y = acc.y * inv + z.y + bb.y;
    o.z = acc.z * inv + z.z + bb.z;
    o.w = acc.w * inv + z.w + bb.w;
    if (RELU) {
        o.x = fmaxf(o.x, 0.f); o.y = fmaxf(o.y, 0.f);
        o.z = fmaxf(o.z, 0.f); o.w = fmaxf(o.w, 0.f);
    }
    out[(size_t)node * C4 + lane] = o;
}

// ---------------------------------------------------------------------------
extern "C" void kernel_launch(void* const* d_in, const int* in_sizes, int n_in,
                              void* d_out, int out_size) {
    const float* x   = (const float*)d_in[0];
    const int*   ei  = (const int*)d_in[1];
    const float* Wl0 = (const float*)d_in[2];
    const float* Wr0 = (const float*)d_in[3];
    const float* b0  = (const float*)d_in[4];
    const float* Wl1 = (const float*)d_in[5];
    const float* Wr1 = (const float*)d_in[6];
    const float* b1  = (const float*)d_in[7];
    const float* Wl2 = (const float*)d_in[8];
    const float* Wr2 = (const float*)d_in[9];
    const float* b2  = (const float*)d_in[10];
    float* out = (float*)d_out;

    const int* src = ei;
    const int* dst = ei + NE;

    float *yz, *h, *wcat;
    int *cnt, *offs, *cursor, *csrc, *bsum;
    cudaGetSymbolAddress((void**)&yz,     g_yz);
    cudaGetSymbolAddress((void**)&h,      g_h);
    cudaGetSymbolAddress((void**)&wcat,   g_wcat);
    cudaGetSymbolAddress((void**)&cnt,    g_cnt);
    cudaGetSymbolAddress((void**)&offs,   g_offs);
    cudaGetSymbolAddress((void**)&cursor, g_cursor);
    cudaGetSymbolAddress((void**)&csrc,   g_csrc);
    cudaGetSymbolAddress((void**)&bsum,   g_bsum);

    const int T = 256;
    const size_t WSZ = 128 * 128 * sizeof(float);

    // ---- build CSR (edges -> sorted-by-dst src list) ----
    zero_cnt<<<(NN + T - 1) / T, T>>>(cnt);
    count_deg<<<(NE + T - 1) / T, T>>>(dst, cnt);
    scan_a<<<NBLK, SCAN_B>>>(cnt, offs, bsum);
    scan_b<<<1, 128>>>(bsum);
    scan_c<<<(NN + T - 1) / T, T>>>(offs, bsum, cursor);
    place_edges<<<(NE + T - 1) / T, T>>>(src, dst, cursor, csrc);

    dim3 gM(4, NN_PAD / 128);    // N = 256
    dim3 gM1(2, NN_PAD / 128);   // N = 128

    // ---- layer 0 ----
    cudaMemcpyAsync(wcat, Wl0, WSZ, cudaMemcpyDeviceToDevice);
    cudaMemcpyAsync(wcat + 128 * 128, Wr0, WSZ, cudaMemcpyDeviceToDevice);
    tf32gemm<<<gM, T>>>(x, wcat, yz, NN, 256);
    agg_combine<32, true><<<(NN * 32 + T - 1) / T, T>>>(
        (const float4*)yz, csrc, offs, b0, (float4*)h);

    // ---- layer 1 ----
    cudaMemcpyAsync(wcat, Wl1, WSZ, cudaMemcpyDeviceToDevice);
    cudaMemcpyAsync(wcat + 128 * 128, Wr1, WSZ, cudaMemcpyDeviceToDevice);
    tf32gemm<<<gM, T>>>(h, wcat, yz, NN, 256);
    agg_combine<32, true><<<(NN * 32 + T - 1) / T, T>>>(
        (const float4*)yz, csrc, offs, b1, (float4*)h);

    // ---- layer 2 (d_out = 64, no relu) ----
    cudaMemcpyAsync(wcat, Wl2, WSZ / 2, cudaMemcpyDeviceToDevice);
    cudaMemcpyAsync(wcat + 64 * 128, Wr2, WSZ / 2, cudaMemcpyDeviceToDevice);
    tf32gemm<<<gM1, T>>>(h, wcat, yz, NN, 128);
    agg_combine<16, false><<<(NN * 16 + T - 1) / T, T>>>(
        (const float4*)yz, csrc, offs, b2, (float4*)out);
}